// round 4
// baseline (speedup 1.0000x reference)
#include <cuda_runtime.h>
#include <cstdint>

// Problem dims
#define CI    32
#define HW    56
#define CO    64
#define KK    288          // CI*3*3
#define LL    3136         // 56*56
#define ROWS  200704       // CO*LL
#define NP    57802752     // ROWS*KK

// flip iff (bits64 >> 12) < MTH  <=>  u_f64 < float64(1e-3*8)
#define MTH   36028797018964ULL

// Scratch (device globals: no allocations allowed)
__device__ float    g_wq[CO * KK];
__device__ float    g_c[NP];          // 231 MB cumsum storage
__device__ float    g_y[ROWS];
__device__ unsigned g_maxp, g_maxc, g_maxy;
__device__ uint2    g_keys[6];        // (ku, klo) for P, C, Y stages

// ---------------- Threefry2x32 (exact JAX rotation/key schedule) ----------------
__device__ __forceinline__ void tf2x32(uint32_t k0, uint32_t k1,
                                       uint32_t x0, uint32_t x1,
                                       uint32_t& o0, uint32_t& o1) {
    uint32_t ks2 = k0 ^ k1 ^ 0x1BD11BDAu;
#define TFR(r) { x0 += x1; x1 = __funnelshift_l(x1, x1, (r)); x1 ^= x0; }
    x0 += k0; x1 += k1;
    TFR(13) TFR(15) TFR(26) TFR(6)
    x0 += k1;  x1 += ks2 + 1u;
    TFR(17) TFR(29) TFR(16) TFR(24)
    x0 += ks2; x1 += k0 + 2u;
    TFR(13) TFR(15) TFR(26) TFR(6)
    x0 += k0;  x1 += k1 + 3u;
    TFR(17) TFR(29) TFR(16) TFR(24)
    x0 += k1;  x1 += ks2 + 4u;
    TFR(13) TFR(15) TFR(26) TFR(6)
    x0 += ks2; x1 += k0 + 5u;
#undef TFR
    o0 = x0; o1 = x1;
}

// ---------------- bitflip_fi element under x64 defaults ----------------
// uniform -> float64 64-bit draw; randint -> int64, pos = low word & 7.
// Partitionable counters: element idx -> (hi, lo) = (0, idx).
__device__ __forceinline__ float bitflip(float x, float scale,
                                         uint2 ku, uint2 klo, uint32_t idx) {
    uint32_t ua, ub, pa, pb;
    tf2x32(ku.x,  ku.y,  0u, idx, ua, ub);   // 64-bit draw for u
    tf2x32(klo.x, klo.y, 0u, idx, pa, pb);   // 64-bit draw for pos (low word used)
    uint64_t bits64 = ((uint64_t)ua << 32) | (uint64_t)ub;
    bool flip = (bits64 >> 12) < MTH;        // u < 0.008 (f64), integer-exact
    int pos = (int)(pb & 7u);                // lower_bits64 % 8

    float t = __fdiv_rn(x, scale);
    float r = rintf(t);                      // lax.round: half-to-even
    r = fminf(127.0f, fmaxf(-128.0f, r));    // clip after round
    int q  = (int)r;
    int qt = q & 255;
    int qf = qt ^ (flip ? (1 << pos) : 0);
    float qs = (float)((qf >= 128) ? (qf - 256) : qf);
    float y  = __fmul_rn(qs, scale);
    // STE forward: x + (y - x), computed literally (NOT algebraically == y)
    return __fadd_rn(x, __fsub_rn(y, x));
}

__device__ __forceinline__ float get_scale(const unsigned* bits) {
    return __fadd_rn(__fdiv_rn(__uint_as_float(*bits), 127.0f), 1e-12f);
}

// ---------------- K0: reset accumulators, derive subkeys (partitionable) ----------------
__global__ void k_init() {
    g_maxp = 0u; g_maxc = 0u; g_maxy = 0u;
    // root = key(42) = (0, 42); foldlike split(root,3)[i] = TF(root,(0,i)), both words
    uint2 ks[3];
    for (uint32_t i = 0; i < 3; i++) tf2x32(0u, 42u, 0u, i, ks[i].x, ks[i].y);
    for (int i = 0; i < 3; i++) {
        uint2 ku, kr, klo;
        tf2x32(ks[i].x, ks[i].y, 0u, 0u, ku.x, ku.y);   // split(k)[0] -> uniform key
        tf2x32(ks[i].x, ks[i].y, 0u, 1u, kr.x, kr.y);   // split(k)[1] -> randint key
        tf2x32(kr.x,    kr.y,    0u, 1u, klo.x, klo.y); // split(kr)[1] -> lower_bits key
        g_keys[2 * i]     = ku;
        g_keys[2 * i + 1] = klo;
    }
}

// ---------------- K1: weight quantization (quant_ste) ----------------
__global__ void k_wq(const float* __restrict__ w) {
    __shared__ float red[256];
    __shared__ float s_scale;
    float m = 0.0f;
    for (int i = threadIdx.x; i < CO * KK; i += 256) m = fmaxf(m, fabsf(w[i]));
    red[threadIdx.x] = m; __syncthreads();
    for (int s = 128; s > 0; s >>= 1) {
        if (threadIdx.x < s) red[threadIdx.x] = fmaxf(red[threadIdx.x], red[threadIdx.x + s]);
        __syncthreads();
    }
    if (threadIdx.x == 0) s_scale = __fadd_rn(__fdiv_rn(red[0], 127.0f), 1e-12f);
    __syncthreads();
    float sc = s_scale;
    for (int i = threadIdx.x; i < CO * KK; i += 256) {
        float ww = w[i];
        float r  = rintf(__fdiv_rn(ww, sc));
        r = fminf(127.0f, fmaxf(-128.0f, r));
        float q  = __fmul_rn(r, sc);
        g_wq[i]  = __fadd_rn(ww, __fsub_rn(q, ww));   // STE forward, literal
    }
}

// ---------------- K2: max|p| = max_k( max_l|xcol| * max_co|wq| ) ----------------
__global__ void k_scalep(const float* __restrict__ x) {
    int k = blockIdx.x;
    int c = k / 9, t = k % 9, ki = t / 3, kj = t % 3;
    __shared__ float red[128];
    float m = 0.0f;
    for (int l = threadIdx.x; l < LL; l += 128) {
        int oh = l / HW, ow = l % HW;
        int ih = oh + ki - 1, iw = ow + kj - 1;
        float v = 0.0f;
        if ((unsigned)ih < HW && (unsigned)iw < HW) v = x[(c * HW + ih) * HW + iw];
        m = fmaxf(m, fabsf(v));
    }
    red[threadIdx.x] = m; __syncthreads();
    for (int s = 64; s > 0; s >>= 1) {
        if (threadIdx.x < s) red[threadIdx.x] = fmaxf(red[threadIdx.x], red[threadIdx.x + s]);
        __syncthreads();
    }
    if (threadIdx.x == 0) {
        float wm = 0.0f;
        for (int co = 0; co < CO; co++) wm = fmaxf(wm, fabsf(g_wq[co * KK + k]));
        float p = __fmul_rn(red[0], wm);   // exact: fp mul rounding is monotone
        atomicMax(&g_maxp, __float_as_uint(p));
    }
}

// ---------------- K3: p = x*wq, bitflip, exact associative-scan tree, store c ----------------
__global__ void __launch_bounds__(128) k_main(const float* __restrict__ x) {
    const int r  = blockIdx.x;
    const int co = r / LL, l = r % LL;
    const int oh = l / HW, ow = l % HW;
    __shared__ float lv[574];   // scan levels: 288+144+72+36+18+9+4+2+1
    __shared__ float red[128];

    const float scale_p = get_scale(&g_maxp);
    const uint2 ku  = g_keys[0];
    const uint2 klo = g_keys[1];

    for (int k = threadIdx.x; k < KK; k += 128) {
        int c = k / 9, t = k % 9, ki = t / 3, kj = t % 3;
        int ih = oh + ki - 1, iw = ow + kj - 1;
        float xv = ((unsigned)ih < HW && (unsigned)iw < HW) ? x[(c * HW + ih) * HW + iw] : 0.0f;
        float p  = __fmul_rn(xv, g_wq[co * KK + k]);
        uint32_t idx = (uint32_t)r * (uint32_t)KK + (uint32_t)k;  // flat C-order index
        lv[k] = bitflip(p, scale_p, ku, klo, idx);
    }
    __syncthreads();

    // Exact replication of jax associative_scan (Brent-Kung) over n=288
    const int OFF[9] = {0, 288, 432, 504, 540, 558, 567, 571, 573};
    const int SZ[9]  = {288, 144, 72, 36, 18, 9, 4, 2, 1};
    // up-sweep: reduced[i] = a[2i] + a[2i+1]
    for (int t = 0; t < 8; t++) {
        for (int i = threadIdx.x; i < SZ[t + 1]; i += 128)
            lv[OFF[t + 1] + i] = __fadd_rn(lv[OFF[t] + 2 * i], lv[OFF[t] + 2 * i + 1]);
        __syncthreads();
    }
    // down-sweep: s[0]=x0, s[2i+1]=child[i], s[2i+2]=child[i]+x[2i+2]
    for (int t = 7; t >= 0; t--) {
        int n = SZ[t];
        for (int i = threadIdx.x; i < SZ[t + 1]; i += 128) {
            float sc = lv[OFF[t + 1] + i];
            bool has = (2 * i + 2 < n);
            float ev = 0.0f;
            if (has) ev = __fadd_rn(sc, lv[OFF[t] + 2 * i + 2]);
            lv[OFF[t] + 2 * i + 1] = sc;
            if (has) lv[OFF[t] + 2 * i + 2] = ev;
        }
        __syncthreads();
    }
    // write c row + track max|c|
    float m = 0.0f;
    for (int k = threadIdx.x; k < KK; k += 128) {
        float cv = lv[k];
        g_c[(size_t)r * KK + k] = cv;
        m = fmaxf(m, fabsf(cv));
    }
    red[threadIdx.x] = m; __syncthreads();
    for (int s = 64; s > 0; s >>= 1) {
        if (threadIdx.x < s) red[threadIdx.x] = fmaxf(red[threadIdx.x], red[threadIdx.x + s]);
        __syncthreads();
    }
    if (threadIdx.x == 0) atomicMax(&g_maxc, __float_as_uint(red[0]));
}

// ---------------- K4: c_fi, y = c_fi[287] + sum_{k=1..286}(c_fi - c) ----------------
__global__ void __launch_bounds__(128) k_yrow() {
    const int r = blockIdx.x;
    __shared__ float red[128];
    __shared__ float s_last;

    const float scale_c = get_scale(&g_maxc);
    const uint2 ku  = g_keys[2];
    const uint2 klo = g_keys[3];

    float acc = 0.0f;
    for (int k = threadIdx.x; k < KK; k += 128) {
        if (k == 0) continue;                 // c_fi[0] never used
        float cv = g_c[(size_t)r * KK + k];
        uint32_t idx = (uint32_t)r * (uint32_t)KK + (uint32_t)k;
        float cf = bitflip(cv, scale_c, ku, klo, idx);
        if (k == KK - 1) s_last = cf;         // y_sum = c_fi[..., -1]
        else acc = __fadd_rn(acc, __fsub_rn(cf, cv));
    }
    red[threadIdx.x] = acc; __syncthreads();
    for (int s = 64; s > 0; s >>= 1) {
        if (threadIdx.x < s) red[threadIdx.x] = __fadd_rn(red[threadIdx.x], red[threadIdx.x + s]);
        __syncthreads();
    }
    if (threadIdx.x == 0) {
        float y = __fadd_rn(s_last, red[0]);
        g_y[r] = y;
        atomicMax(&g_maxy, __float_as_uint(fabsf(y)));
    }
}

// ---------------- K5: final output bitflip ----------------
__global__ void k_out(float* __restrict__ out) {
    int i = blockIdx.x * 256 + threadIdx.x;
    if (i >= ROWS) return;
    const float scale_y = get_scale(&g_maxy);
    out[i] = bitflip(g_y[i], scale_y, g_keys[4], g_keys[5], (uint32_t)i);
}

// ---------------- launch ----------------
extern "C" void kernel_launch(void* const* d_in, const int* in_sizes, int n_in,
                              void* d_out, int out_size) {
    const float* x = (const float*)d_in[0];
    const float* w = (const float*)d_in[1];
    if (n_in >= 2 && in_sizes[0] == CO * KK && in_sizes[1] == CI * HW * HW) {
        // defensive: metadata order flipped
        const float* tmp = x; x = w; w = tmp;
    }
    k_init<<<1, 1>>>();
    k_wq<<<1, 256>>>(w);
    k_scalep<<<KK, 128>>>(x);
    k_main<<<ROWS, 128>>>(x);
    k_yrow<<<ROWS, 128>>>();
    k_out<<<(ROWS + 255) / 256, 256>>>((float*)d_out);
}

// round 5
// speedup vs baseline: 1.2103x; 1.2103x over previous
#include <cuda_runtime.h>
#include <cstdint>

// Problem dims
#define CI    32
#define HW    56
#define CO    64
#define KK    288          // CI*3*3
#define LL    3136         // 56*56
#define ROWS  200704       // CO*LL
#define NP    57802752     // ROWS*KK

// flip iff (bits64 >> 12) < MTH  <=>  u_f64 < float64(1e-3*8)
#define MTH   36028797018964ULL

// Scratch (device globals: no allocations allowed)
__device__ float    g_wq[CO * KK];
__device__ float    g_c[NP];          // 231 MB cumsum storage
__device__ float    g_y[ROWS];
__device__ unsigned g_maxp, g_maxc, g_maxy;
__device__ uint2    g_keys[6];        // (ku, klo) for P, C, Y stages

// ---------------- Threefry2x32 (exact JAX rotation/key schedule) ----------------
__device__ __forceinline__ void tf2x32(uint32_t k0, uint32_t k1,
                                       uint32_t x0, uint32_t x1,
                                       uint32_t& o0, uint32_t& o1) {
    uint32_t ks2 = k0 ^ k1 ^ 0x1BD11BDAu;
#define TFR(r) { x0 += x1; x1 = __funnelshift_l(x1, x1, (r)); x1 ^= x0; }
    x0 += k0; x1 += k1;
    TFR(13) TFR(15) TFR(26) TFR(6)
    x0 += k1;  x1 += ks2 + 1u;
    TFR(17) TFR(29) TFR(16) TFR(24)
    x0 += ks2; x1 += k0 + 2u;
    TFR(13) TFR(15) TFR(26) TFR(6)
    x0 += k0;  x1 += k1 + 3u;
    TFR(17) TFR(29) TFR(16) TFR(24)
    x0 += k1;  x1 += ks2 + 4u;
    TFR(13) TFR(15) TFR(26) TFR(6)
    x0 += ks2; x1 += k0 + 5u;
#undef TFR
    o0 = x0; o1 = x1;
}

// ---------------- bitflip_fi (x64 defaults) with LAZY pos-draw ----------------
// uniform -> f64 64-bit draw (always); randint pos-draw only if any lane flips.
// CALLER GUARANTEE: every lane of the warp executes this call (converged warp).
__device__ __forceinline__ float bitflip(float x, float scale,
                                         uint2 ku, uint2 klo, uint32_t idx) {
    uint32_t ua, ub;
    tf2x32(ku.x, ku.y, 0u, idx, ua, ub);          // 64-bit draw for u
    uint64_t bits64 = ((uint64_t)ua << 32) | (uint64_t)ub;
    bool flip = (bits64 >> 12) < MTH;             // u < 0.008 (f64), integer-exact
    int m = 0;
    if (__ballot_sync(0xffffffffu, flip)) {       // warp-uniform: ~22.6% of warps
        uint32_t pa, pb;
        tf2x32(klo.x, klo.y, 0u, idx, pa, pb);    // pos = lower_bits64 % 8 = pb & 7
        if (flip) m = 1 << (int)(pb & 7u);
    }
    float t = __fdiv_rn(x, scale);
    float r = rintf(t);                           // lax.round: half-to-even
    r = fminf(127.0f, fmaxf(-128.0f, r));         // clip after round
    int q  = (int)r;
    int qf = (q & 255) ^ m;
    float qs = (float)((qf >= 128) ? (qf - 256) : qf);
    float y  = __fmul_rn(qs, scale);
    // STE forward: x + (y - x), computed literally (NOT algebraically == y)
    return __fadd_rn(x, __fsub_rn(y, x));
}

__device__ __forceinline__ float get_scale(const unsigned* bits) {
    return __fadd_rn(__fdiv_rn(__uint_as_float(*bits), 127.0f), 1e-12f);
}

// ---------------- K0: reset accumulators, derive subkeys (partitionable) ----------------
__global__ void k_init() {
    g_maxp = 0u; g_maxc = 0u; g_maxy = 0u;
    // root = key(42) = (0, 42); foldlike split(root,3)[i] = TF(root,(0,i)), both words
    uint2 ks[3];
    for (uint32_t i = 0; i < 3; i++) tf2x32(0u, 42u, 0u, i, ks[i].x, ks[i].y);
    for (int i = 0; i < 3; i++) {
        uint2 ku, kr, klo;
        tf2x32(ks[i].x, ks[i].y, 0u, 0u, ku.x, ku.y);   // split(k)[0] -> uniform key
        tf2x32(ks[i].x, ks[i].y, 0u, 1u, kr.x, kr.y);   // split(k)[1] -> randint key
        tf2x32(kr.x,    kr.y,    0u, 1u, klo.x, klo.y); // split(kr)[1] -> lower_bits key
        g_keys[2 * i]     = ku;
        g_keys[2 * i + 1] = klo;
    }
}

// ---------------- K1: weight quantization (quant_ste) ----------------
__global__ void k_wq(const float* __restrict__ w) {
    __shared__ float red[256];
    __shared__ float s_scale;
    float m = 0.0f;
    for (int i = threadIdx.x; i < CO * KK; i += 256) m = fmaxf(m, fabsf(w[i]));
    red[threadIdx.x] = m; __syncthreads();
    for (int s = 128; s > 0; s >>= 1) {
        if (threadIdx.x < s) red[threadIdx.x] = fmaxf(red[threadIdx.x], red[threadIdx.x + s]);
        __syncthreads();
    }
    if (threadIdx.x == 0) s_scale = __fadd_rn(__fdiv_rn(red[0], 127.0f), 1e-12f);
    __syncthreads();
    float sc = s_scale;
    for (int i = threadIdx.x; i < CO * KK; i += 256) {
        float ww = w[i];
        float r  = rintf(__fdiv_rn(ww, sc));
        r = fminf(127.0f, fmaxf(-128.0f, r));
        float q  = __fmul_rn(r, sc);
        g_wq[i]  = __fadd_rn(ww, __fsub_rn(q, ww));   // STE forward, literal
    }
}

// ---------------- K2: max|p| = max_k( max_l|xcol| * max_co|wq| ) ----------------
__global__ void k_scalep(const float* __restrict__ x) {
    int k = blockIdx.x;
    int c = k / 9, t = k % 9, ki = t / 3, kj = t % 3;
    __shared__ float red[128];
    float m = 0.0f;
    for (int l = threadIdx.x; l < LL; l += 128) {
        int oh = l / HW, ow = l % HW;
        int ih = oh + ki - 1, iw = ow + kj - 1;
        float v = 0.0f;
        if ((unsigned)ih < HW && (unsigned)iw < HW) v = x[(c * HW + ih) * HW + iw];
        m = fmaxf(m, fabsf(v));
    }
    red[threadIdx.x] = m; __syncthreads();
    for (int s = 64; s > 0; s >>= 1) {
        if (threadIdx.x < s) red[threadIdx.x] = fmaxf(red[threadIdx.x], red[threadIdx.x + s]);
        __syncthreads();
    }
    if (threadIdx.x == 0) {
        float wm = 0.0f;
        for (int co = 0; co < CO; co++) wm = fmaxf(wm, fabsf(g_wq[co * KK + k]));
        float p = __fmul_rn(red[0], wm);   // exact: fp mul rounding is monotone
        atomicMax(&g_maxp, __float_as_uint(p));
    }
}

// ---------------- K3: p = x*wq, bitflip, exact associative-scan tree, store c ----------------
// 128 threads, k-loop: iters 0/1 are full warps 0-3; iter 2 is exactly warp 0 (k=256..287).
// Every warp executing the bitflip call is fully converged -> ballot-safe.
__global__ void __launch_bounds__(128) k_main(const float* __restrict__ x) {
    const int r  = blockIdx.x;
    const int co = r / LL, l = r % LL;
    const int oh = l / HW, ow = l % HW;
    __shared__ float lv[574];   // scan levels: 288+144+72+36+18+9+4+2+1
    __shared__ float red[128];

    const float scale_p = get_scale(&g_maxp);
    const uint2 ku  = g_keys[0];
    const uint2 klo = g_keys[1];

    for (int k = threadIdx.x; k < KK; k += 128) {
        int c = k / 9, t = k % 9, ki = t / 3, kj = t % 3;
        int ih = oh + ki - 1, iw = ow + kj - 1;
        float xv = ((unsigned)ih < HW && (unsigned)iw < HW) ? x[(c * HW + ih) * HW + iw] : 0.0f;
        float p  = __fmul_rn(xv, g_wq[co * KK + k]);
        uint32_t idx = (uint32_t)r * (uint32_t)KK + (uint32_t)k;  // flat C-order index
        lv[k] = bitflip(p, scale_p, ku, klo, idx);
    }
    __syncthreads();

    // Exact replication of jax associative_scan (Brent-Kung) over n=288
    const int OFF[9] = {0, 288, 432, 504, 540, 558, 567, 571, 573};
    const int SZ[9]  = {288, 144, 72, 36, 18, 9, 4, 2, 1};
    // up-sweep: reduced[i] = a[2i] + a[2i+1]
    for (int t = 0; t < 8; t++) {
        for (int i = threadIdx.x; i < SZ[t + 1]; i += 128)
            lv[OFF[t + 1] + i] = __fadd_rn(lv[OFF[t] + 2 * i], lv[OFF[t] + 2 * i + 1]);
        __syncthreads();
    }
    // down-sweep: s[0]=x0, s[2i+1]=child[i], s[2i+2]=child[i]+x[2i+2]
    for (int t = 7; t >= 0; t--) {
        int n = SZ[t];
        for (int i = threadIdx.x; i < SZ[t + 1]; i += 128) {
            float sc = lv[OFF[t + 1] + i];
            bool has = (2 * i + 2 < n);
            float ev = 0.0f;
            if (has) ev = __fadd_rn(sc, lv[OFF[t] + 2 * i + 2]);
            lv[OFF[t] + 2 * i + 1] = sc;
            if (has) lv[OFF[t] + 2 * i + 2] = ev;
        }
        __syncthreads();
    }
    // write c row + track max|c|
    float m = 0.0f;
    for (int k = threadIdx.x; k < KK; k += 128) {
        float cv = lv[k];
        g_c[(size_t)r * KK + k] = cv;
        m = fmaxf(m, fabsf(cv));
    }
    red[threadIdx.x] = m; __syncthreads();
    for (int s = 64; s > 0; s >>= 1) {
        if (threadIdx.x < s) red[threadIdx.x] = fmaxf(red[threadIdx.x], red[threadIdx.x + s]);
        __syncthreads();
    }
    if (threadIdx.x == 0) atomicMax(&g_maxc, __float_as_uint(red[0]));
}

// ---------------- K4: c_fi, y = c_fi[287] + sum_{k=1..286}(c_fi - c) ----------------
// k==0 is computed (keeps warps converged for the ballot) but excluded by predicate.
__global__ void __launch_bounds__(128) k_yrow() {
    const int r = blockIdx.x;
    __shared__ float red[128];
    __shared__ float s_last;

    const float scale_c = get_scale(&g_maxc);
    const uint2 ku  = g_keys[2];
    const uint2 klo = g_keys[3];

    float acc = 0.0f;
    for (int k = threadIdx.x; k < KK; k += 128) {
        float cv = g_c[(size_t)r * KK + k];
        uint32_t idx = (uint32_t)r * (uint32_t)KK + (uint32_t)k;
        float cf = bitflip(cv, scale_c, ku, klo, idx);
        if (k == KK - 1) s_last = cf;                      // y_sum = c_fi[..., -1]
        else if (k > 0) acc = __fadd_rn(acc, __fsub_rn(cf, cv));
    }
    red[threadIdx.x] = acc; __syncthreads();
    for (int s = 64; s > 0; s >>= 1) {
        if (threadIdx.x < s) red[threadIdx.x] = __fadd_rn(red[threadIdx.x], red[threadIdx.x + s]);
        __syncthreads();
    }
    if (threadIdx.x == 0) {
        float y = __fadd_rn(s_last, red[0]);
        g_y[r] = y;
        atomicMax(&g_maxy, __float_as_uint(fabsf(y)));
    }
}

// ---------------- K5: final output bitflip (ROWS = 784*256, all warps full) ----------------
__global__ void k_out(float* __restrict__ out) {
    int i = blockIdx.x * 256 + threadIdx.x;
    if (i >= ROWS) return;
    const float scale_y = get_scale(&g_maxy);
    out[i] = bitflip(g_y[i], scale_y, g_keys[4], g_keys[5], (uint32_t)i);
}

// ---------------- launch ----------------
extern "C" void kernel_launch(void* const* d_in, const int* in_sizes, int n_in,
                              void* d_out, int out_size) {
    const float* x = (const float*)d_in[0];
    const float* w = (const float*)d_in[1];
    if (n_in >= 2 && in_sizes[0] == CO * KK && in_sizes[1] == CI * HW * HW) {
        // defensive: metadata order flipped
        const float* tmp = x; x = w; w = tmp;
    }
    k_init<<<1, 1>>>();
    k_wq<<<1, 256>>>(w);
    k_scalep<<<KK, 128>>>(x);
    k_main<<<ROWS, 128>>>(x);
    k_yrow<<<ROWS, 128>>>();
    k_out<<<(ROWS + 255) / 256, 256>>>((float*)d_out);
}

// round 8
// speedup vs baseline: 1.3731x; 1.1346x over previous
#include <cuda_runtime.h>
#include <cstdint>

// Problem dims
#define CI    32
#define HW    56
#define CO    64
#define KK    288          // CI*3*3
#define LL    3136         // 56*56
#define ROWS  200704       // CO*LL
#define NP    57802752     // ROWS*KK

// flip iff (bits64 >> 12) < MTH  <=>  u_f64 < float64(1e-3*8)
#define MTH   36028797018964ULL

// Scratch (device globals: no allocations allowed)
__device__ float    g_wq[CO * KK];
__device__ float    g_c[NP];          // 231 MB cumsum storage
__device__ float    g_y[ROWS];
__device__ unsigned g_maxp, g_maxc, g_maxy;
__device__ uint2    g_keys[6];        // (ku, klo) for P, C, Y stages
__device__ int2     g_tab[KK];        // per-k: x-offset delta, (ki<<8)|kj

// ---------------- Threefry2x32 (exact JAX rotation/key schedule) ----------------
__device__ __forceinline__ void tf2x32(uint32_t k0, uint32_t k1,
                                       uint32_t x0, uint32_t x1,
                                       uint32_t& o0, uint32_t& o1) {
    uint32_t ks2 = k0 ^ k1 ^ 0x1BD11BDAu;
#define TFR(r) { x0 += x1; x1 = __funnelshift_l(x1, x1, (r)); x1 ^= x0; }
    x0 += k0; x1 += k1;
    TFR(13) TFR(15) TFR(26) TFR(6)
    x0 += k1;  x1 += ks2 + 1u;
    TFR(17) TFR(29) TFR(16) TFR(24)
    x0 += ks2; x1 += k0 + 2u;
    TFR(13) TFR(15) TFR(26) TFR(6)
    x0 += k0;  x1 += k1 + 3u;
    TFR(17) TFR(29) TFR(16) TFR(24)
    x0 += k1;  x1 += ks2 + 4u;
    TFR(13) TFR(15) TFR(26) TFR(6)
    x0 += ks2; x1 += k0 + 5u;
#undef TFR
    o0 = x0; o1 = x1;
}

// Exact RN(x/s) in 3 ops given r = RN(1/s) (Markstein; fma required).
__device__ __forceinline__ float div_exact(float x, float s, float r) {
    float q0 = __fmul_rn(x, r);
    float e  = __fmaf_rn(-s, q0, x);
    return __fmaf_rn(e, r, q0);
}

// ---------------- bitflip_fi (x64 defaults) with LAZY pos-draw ----------------
// CALLER GUARANTEE: every lane of the warp executes this call (converged warp).
__device__ __forceinline__ float bitflip(float x, float scale, float rcp,
                                         uint2 ku, uint2 klo, uint32_t idx) {
    uint32_t ua, ub;
    tf2x32(ku.x, ku.y, 0u, idx, ua, ub);          // 64-bit draw for u
    uint64_t bits64 = ((uint64_t)ua << 32) | (uint64_t)ub;
    bool flip = (bits64 >> 12) < MTH;             // u < 0.008 (f64), integer-exact
    int m = 0;
    if (__ballot_sync(0xffffffffu, flip)) {       // warp-uniform: ~22.6% of warps
        uint32_t pa, pb;
        tf2x32(klo.x, klo.y, 0u, idx, pa, pb);    // pos = lower_bits64 % 8 = pb & 7
        if (flip) m = 1 << (int)(pb & 7u);
    }
    float t = div_exact(x, scale, rcp);           // == __fdiv_rn(x, scale), bit-exact
    float r = rintf(t);                           // lax.round: half-to-even
    r = fminf(127.0f, fmaxf(-128.0f, r));         // clip after round
    int q  = (int)r;
    int qf = (q & 255) ^ m;
    float qs = (float)((qf >= 128) ? (qf - 256) : qf);
    float y  = __fmul_rn(qs, scale);
    // STE forward: x + (y - x), computed literally
    return __fadd_rn(x, __fsub_rn(y, x));
}

__device__ __forceinline__ float get_scale(const unsigned* bits) {
    return __fadd_rn(__fdiv_rn(__uint_as_float(*bits), 127.0f), 1e-12f);
}

// ---------------- K0: reset accumulators, subkeys, per-k table ----------------
__global__ void k_init() {
    g_maxp = 0u; g_maxc = 0u; g_maxy = 0u;
    uint2 ks[3];
    for (uint32_t i = 0; i < 3; i++) tf2x32(0u, 42u, 0u, i, ks[i].x, ks[i].y);
    for (int i = 0; i < 3; i++) {
        uint2 ku, kr, klo;
        tf2x32(ks[i].x, ks[i].y, 0u, 0u, ku.x, ku.y);   // split(k)[0] -> uniform key
        tf2x32(ks[i].x, ks[i].y, 0u, 1u, kr.x, kr.y);   // split(k)[1] -> randint key
        tf2x32(kr.x,    kr.y,    0u, 1u, klo.x, klo.y); // split(kr)[1] -> lower_bits key
        g_keys[2 * i]     = ku;
        g_keys[2 * i + 1] = klo;
    }
    for (int k = 0; k < KK; k++) {
        int c = k / 9, t = k % 9, ki = t / 3, kj = t % 3;
        g_tab[k].x = c * (HW * HW) + ki * HW + kj;   // + (oh-1)*56 + (ow-1) at use
        g_tab[k].y = (ki << 8) | kj;
    }
}

// ---------------- K1: weight quantization (quant_ste) ----------------
__global__ void k_wq(const float* __restrict__ w) {
    __shared__ float red[256];
    __shared__ float s_scale;
    float m = 0.0f;
    for (int i = threadIdx.x; i < CO * KK; i += 256) m = fmaxf(m, fabsf(w[i]));
    red[threadIdx.x] = m; __syncthreads();
    for (int s = 128; s > 0; s >>= 1) {
        if (threadIdx.x < s) red[threadIdx.x] = fmaxf(red[threadIdx.x], red[threadIdx.x + s]);
        __syncthreads();
    }
    if (threadIdx.x == 0) s_scale = __fadd_rn(__fdiv_rn(red[0], 127.0f), 1e-12f);
    __syncthreads();
    float sc = s_scale;
    for (int i = threadIdx.x; i < CO * KK; i += 256) {
        float ww = w[i];
        float r  = rintf(__fdiv_rn(ww, sc));
        r = fminf(127.0f, fmaxf(-128.0f, r));
        float q  = __fmul_rn(r, sc);
        g_wq[i]  = __fadd_rn(ww, __fsub_rn(q, ww));   // STE forward, literal
    }
}

// ---------------- K2: max|p| = max_k( max_l|xcol| * max_co|wq| ) ----------------
__global__ void k_scalep(const float* __restrict__ x) {
    int k = blockIdx.x;
    int c = k / 9, t = k % 9, ki = t / 3, kj = t % 3;
    __shared__ float red[128];
    float m = 0.0f;
    for (int l = threadIdx.x; l < LL; l += 128) {
        int oh = l / HW, ow = l % HW;
        int ih = oh + ki - 1, iw = ow + kj - 1;
        float v = 0.0f;
        if ((unsigned)ih < HW && (unsigned)iw < HW) v = x[(c * HW + ih) * HW + iw];
        m = fmaxf(m, fabsf(v));
    }
    red[threadIdx.x] = m; __syncthreads();
    for (int s = 64; s > 0; s >>= 1) {
        if (threadIdx.x < s) red[threadIdx.x] = fmaxf(red[threadIdx.x], red[threadIdx.x + s]);
        __syncthreads();
    }
    if (threadIdx.x == 0) {
        float wm = 0.0f;
        for (int co = 0; co < CO; co++) wm = fmaxf(wm, fabsf(g_wq[co * KK + k]));
        float p = __fmul_rn(red[0], wm);   // exact: fp mul rounding is monotone
        atomicMax(&g_maxp, __float_as_uint(p));
    }
}

// ---------------- K3: p bitflip + exact Brent-Kung scan + store c ----------------
// Loop iters: 0/1 full warps 0-3; iter 2 exactly warp 0 -> ballot-safe everywhere.
__global__ void __launch_bounds__(128) k_main(const float* __restrict__ x) {
    const int r  = blockIdx.x;
    const int co = r / LL, l = r % LL;
    const int oh = l / HW, ow = l % HW;
    __shared__ float lv[574];   // scan levels: 288+144+72+36+18+9+4+2+1
    __shared__ unsigned s_max;
    const int tid = threadIdx.x;

    if (tid == 0) s_max = 0u;

    const float scale_p = get_scale(&g_maxp);
    const float rcp_p   = __frcp_rn(scale_p);
    const uint2 ku  = g_keys[0];
    const uint2 klo = g_keys[1];
    const float* wrow = g_wq + co * KK;
    const int base = (oh - 1) * HW + (ow - 1);
    const uint32_t ridx = (uint32_t)r * (uint32_t)KK;

    if (oh >= 1 && oh < HW - 1 && ow >= 1 && ow < HW - 1) {
        // interior: no bounds checks (87% of blocks)
        for (int k = tid; k < KK; k += 128) {
            int2 tv = g_tab[k];
            float p = __fmul_rn(x[base + tv.x], wrow[k]);
            lv[k] = bitflip(p, scale_p, rcp_p, ku, klo, ridx + (uint32_t)k);
        }
    } else {
        for (int k = tid; k < KK; k += 128) {
            int2 tv = g_tab[k];
            int ki = tv.y >> 8, kj = tv.y & 255;
            float xv = 0.0f;
            if ((unsigned)(oh - 1 + ki) < HW && (unsigned)(ow - 1 + kj) < HW)
                xv = x[base + tv.x];
            float p = __fmul_rn(xv, wrow[k]);
            lv[k] = bitflip(p, scale_p, rcp_p, ku, klo, ridx + (uint32_t)k);
        }
    }
    __syncthreads();                                  // B1

    // ---- up-sweep t=0: 288 -> 144 (block) ----
    for (int i = tid; i < 144; i += 128)
        lv[288 + i] = __fadd_rn(lv[2 * i], lv[2 * i + 1]);
    __syncthreads();                                  // B2
    // ---- up-sweep t=1: 144 -> 72 ----
    if (tid < 72)
        lv[432 + tid] = __fadd_rn(lv[288 + 2 * tid], lv[288 + 2 * tid + 1]);
    __syncthreads();                                  // B3

    // ---- solo warp: up t=2..7 and down t=7..2 ----
    if (tid < 32) {
        const int lid = tid;
        // up: (srcOFF, dstOFF, dstSZ)
        {   // t=2: 432(72) -> 504(36)
            for (int i = lid; i < 36; i += 32)
                lv[504 + i] = __fadd_rn(lv[432 + 2 * i], lv[432 + 2 * i + 1]);
            __syncwarp();
            // t=3: 504(36) -> 540(18)
            if (lid < 18) lv[540 + lid] = __fadd_rn(lv[504 + 2 * lid], lv[504 + 2 * lid + 1]);
            __syncwarp();
            // t=4: 540(18) -> 558(9)
            if (lid < 9) lv[558 + lid] = __fadd_rn(lv[540 + 2 * lid], lv[540 + 2 * lid + 1]);
            __syncwarp();
            // t=5: 558(9) -> 567(4)
            if (lid < 4) lv[567 + lid] = __fadd_rn(lv[558 + 2 * lid], lv[558 + 2 * lid + 1]);
            __syncwarp();
            // t=6: 567(4) -> 571(2)
            if (lid < 2) lv[571 + lid] = __fadd_rn(lv[567 + 2 * lid], lv[567 + 2 * lid + 1]);
            __syncwarp();
            // t=7: 571(2) -> 573(1)
            if (lid < 1) lv[573] = __fadd_rn(lv[571], lv[572]);
            __syncwarp();
        }
        // down-sweep, in-place scan of each level
        {   // t=7: n=2, iters=1
            if (lid < 1) lv[571 + 1] = lv[573];
            __syncwarp();
            // t=6: n=4, iters=2, OFF=567, up=571
            if (lid < 2) {
                float sc = lv[571 + lid];
                bool has = (2 * lid + 2 < 4);
                float ev = has ? __fadd_rn(sc, lv[567 + 2 * lid + 2]) : 0.0f;
                lv[567 + 2 * lid + 1] = sc;
                if (has) lv[567 + 2 * lid + 2] = ev;
            }
            __syncwarp();
            // t=5: n=9, iters=4, OFF=558, up=567
            if (lid < 4) {
                float sc = lv[567 + lid];
                bool has = (2 * lid + 2 < 9);
                float ev = has ? __fadd_rn(sc, lv[558 + 2 * lid + 2]) : 0.0f;
                lv[558 + 2 * lid + 1] = sc;
                if (has) lv[558 + 2 * lid + 2] = ev;
            }
            __syncwarp();
            // t=4: n=18, iters=9, OFF=540, up=558
            if (lid < 9) {
                float sc = lv[558 + lid];
                bool has = (2 * lid + 2 < 18);
                float ev = has ? __fadd_rn(sc, lv[540 + 2 * lid + 2]) : 0.0f;
                lv[540 + 2 * lid + 1] = sc;
                if (has) lv[540 + 2 * lid + 2] = ev;
            }
            __syncwarp();
            // t=3: n=36, iters=18, OFF=504, up=540
            if (lid < 18) {
                float sc = lv[540 + lid];
                bool has = (2 * lid + 2 < 36);
                float ev = has ? __fadd_rn(sc, lv[504 + 2 * lid + 2]) : 0.0f;
                lv[504 + 2 * lid + 1] = sc;
                if (has) lv[504 + 2 * lid + 2] = ev;
            }
            __syncwarp();
            // t=2: n=72, iters=36, OFF=432, up=504
            for (int i = lid; i < 36; i += 32) {
                float sc = lv[504 + i];
                bool has = (2 * i + 2 < 72);
                float ev = has ? __fadd_rn(sc, lv[432 + 2 * i + 2]) : 0.0f;
                lv[432 + 2 * i + 1] = sc;
                if (has) lv[432 + 2 * i + 2] = ev;
            }
        }
    }
    __syncthreads();                                  // B4
    // ---- down t=1: n=144, iters=72, OFF=288, up=432 ----
    if (tid < 72) {
        float sc = lv[432 + tid];
        bool has = (2 * tid + 2 < 144);
        float ev = has ? __fadd_rn(sc, lv[288 + 2 * tid + 2]) : 0.0f;
        lv[288 + 2 * tid + 1] = sc;
        if (has) lv[288 + 2 * tid + 2] = ev;
    }
    __syncthreads();                                  // B5
    // ---- down t=0: n=288, iters=144, OFF=0, up=288 ----
    for (int i = tid; i < 144; i += 128) {
        float sc = lv[288 + i];
        bool has = (2 * i + 2 < 288);
        float ev = has ? __fadd_rn(sc, lv[2 * i + 2]) : 0.0f;
        lv[2 * i + 1] = sc;
        if (has) lv[2 * i + 2] = ev;
    }
    __syncthreads();                                  // B6

    // write c row + track max|c| via shuffle + shared atomic
    float m = 0.0f;
    for (int k = tid; k < KK; k += 128) {
        float cv = lv[k];
        g_c[(size_t)r * KK + k] = cv;
        m = fmaxf(m, fabsf(cv));
    }
    #pragma unroll
    for (int d = 16; d > 0; d >>= 1)
        m = fmaxf(m, __shfl_xor_sync(0xffffffffu, m, d));
    if ((tid & 31) == 0) atomicMax(&s_max, __float_as_uint(m));
    __syncthreads();                                  // B7
    if (tid == 0) atomicMax(&g_maxc, s_max);
}

// ---------------- K4: c_fi, y = c_fi[287] + sum_{k=1..286}(c_fi - c) ----------------
__global__ void __launch_bounds__(128) k_yrow() {
    const int r = blockIdx.x;
    __shared__ float warp_acc[4];
    __shared__ float s_last;
    const int tid = threadIdx.x;

    const float scale_c = get_scale(&g_maxc);
    const float rcp_c   = __frcp_rn(scale_c);
    const uint2 ku  = g_keys[2];
    const uint2 klo = g_keys[3];
    const uint32_t ridx = (uint32_t)r * (uint32_t)KK;

    float acc = 0.0f;
    for (int k = tid; k < KK; k += 128) {
        float cv = g_c[(size_t)r * KK + k];
        float cf = bitflip(cv, scale_c, rcp_c, ku, klo, ridx + (uint32_t)k);
        if (k == KK - 1) s_last = cf;                      // y_sum = c_fi[..., -1]
        else if (k > 0) acc = __fadd_rn(acc, __fsub_rn(cf, cv));
    }
    #pragma unroll
    for (int d = 16; d > 0; d >>= 1)
        acc = __fadd_rn(acc, __shfl_xor_sync(0xffffffffu, acc, d));
    if ((tid & 31) == 0) warp_acc[tid >> 5] = acc;
    __syncthreads();
    if (tid == 0) {
        float s = __fadd_rn(__fadd_rn(__fadd_rn(warp_acc[0], warp_acc[1]),
                                      warp_acc[2]), warp_acc[3]);
        float y = __fadd_rn(s_last, s);
        g_y[r] = y;
        atomicMax(&g_maxy, __float_as_uint(fabsf(y)));
    }
}

// ---------------- K5: final output bitflip (ROWS = 784*256, all warps full) ----------------
__global__ void k_out(float* __restrict__ out) {
    int i = blockIdx.x * 256 + threadIdx.x;
    if (i >= ROWS) return;
    const float scale_y = get_scale(&g_maxy);
    const float rcp_y   = __frcp_rn(scale_y);
    out[i] = bitflip(g_y[i], scale_y, rcp_y, g_keys[4], g_keys[5], (uint32_t)i);
}

// ---------------- launch ----------------
extern "C" void kernel_launch(void* const* d_in, const int* in_sizes, int n_in,
                              void* d_out, int out_size) {
    const float* x = (const float*)d_in[0];
    const float* w = (const float*)d_in[1];
    if (n_in >= 2 && in_sizes[0] == CO * KK && in_sizes[1] == CI * HW * HW) {
        const float* tmp = x; x = w; w = tmp;
    }
    k_init<<<1, 1>>>();
    k_wq<<<1, 256>>>(w);
    k_scalep<<<KK, 128>>>(x);
    k_main<<<ROWS, 128>>>(x);
    k_yrow<<<ROWS, 128>>>();
    k_out<<<(ROWS + 255) / 256, 256>>>((float*)d_out);
}

// round 10
// speedup vs baseline: 1.7705x; 1.2894x over previous
#include <cuda_runtime.h>
#include <cstdint>

// Problem dims
#define CI    32
#define HW    56
#define CO    64
#define KK    288          // CI*3*3
#define LL    3136         // 56*56
#define ROWS  200704       // CO*LL
#define NP    57802752     // ROWS*KK

// flip iff (bits64 >> 12) < MTH  <=>  u_f64 < float64(1e-3*8)
#define MTH   36028797018964ULL

// Scratch (device globals: no allocations allowed)
__device__ float    g_wq[CO * KK];
__device__ float    g_c[NP];          // 231 MB cumsum storage
__device__ float    g_y[ROWS];
__device__ unsigned g_maxp, g_maxc, g_maxy;
__device__ uint2    g_keys[6];        // (ku, klo) for P, C, Y stages
__device__ int2     g_tab[KK];        // per-k: x-offset delta, (ki<<8)|kj

// ---------------- Threefry2x32 (exact JAX rotation/key schedule) ----------------
__device__ __forceinline__ void tf2x32(uint32_t k0, uint32_t k1,
                                       uint32_t x0, uint32_t x1,
                                       uint32_t& o0, uint32_t& o1) {
    uint32_t ks2 = k0 ^ k1 ^ 0x1BD11BDAu;
#define TFR(r) { x0 += x1; x1 = __funnelshift_l(x1, x1, (r)); x1 ^= x0; }
    x0 += k0; x1 += k1;
    TFR(13) TFR(15) TFR(26) TFR(6)
    x0 += k1;  x1 += ks2 + 1u;
    TFR(17) TFR(29) TFR(16) TFR(24)
    x0 += ks2; x1 += k0 + 2u;
    TFR(13) TFR(15) TFR(26) TFR(6)
    x0 += k0;  x1 += k1 + 3u;
    TFR(17) TFR(29) TFR(16) TFR(24)
    x0 += k1;  x1 += ks2 + 4u;
    TFR(13) TFR(15) TFR(26) TFR(6)
    x0 += ks2; x1 += k0 + 5u;
#undef TFR
    o0 = x0; o1 = x1;
}

// Exact RN(x/s) in 3 ops given r = RN(1/s) (Markstein; fma required).
__device__ __forceinline__ float div_exact(float x, float s, float r) {
    float q0 = __fmul_rn(x, r);
    float e  = __fmaf_rn(-s, q0, x);
    return __fmaf_rn(e, r, q0);
}

// ---------------- bitflip_fi (x64 defaults) with LAZY pos-draw ----------------
// CALLER GUARANTEE: every lane of the warp executes this call (converged warp).
__device__ __forceinline__ float bitflip(float x, float scale, float rcp,
                                         uint2 ku, uint2 klo, uint32_t idx) {
    uint32_t ua, ub;
    tf2x32(ku.x, ku.y, 0u, idx, ua, ub);          // 64-bit draw for u
    uint64_t bits64 = ((uint64_t)ua << 32) | (uint64_t)ub;
    bool flip = (bits64 >> 12) < MTH;             // u < 0.008 (f64), integer-exact
    int m = 0;
    if (__ballot_sync(0xffffffffu, flip)) {       // warp-uniform: ~22.6% of warps
        uint32_t pa, pb;
        tf2x32(klo.x, klo.y, 0u, idx, pa, pb);    // pos = lower_bits64 % 8 = pb & 7
        if (flip) m = 1 << (int)(pb & 7u);
    }
    float t = div_exact(x, scale, rcp);           // == __fdiv_rn(x, scale), bit-exact
    float r = rintf(t);                           // lax.round: half-to-even
    r = fminf(127.0f, fmaxf(-128.0f, r));         // clip after round
    int q  = (int)r;
    int qf = (q & 255) ^ m;
    float qs = (float)((qf >= 128) ? (qf - 256) : qf);
    float y  = __fmul_rn(qs, scale);
    // STE forward: x + (y - x), computed literally
    return __fadd_rn(x, __fsub_rn(y, x));
}

__device__ __forceinline__ float get_scale(const unsigned* bits) {
    return __fadd_rn(__fdiv_rn(__uint_as_float(*bits), 127.0f), 1e-12f);
}

// ---------------- K0: reset accumulators, subkeys, per-k table ----------------
__global__ void k_init() {
    g_maxp = 0u; g_maxc = 0u; g_maxy = 0u;
    uint2 ks[3];
    for (uint32_t i = 0; i < 3; i++) tf2x32(0u, 42u, 0u, i, ks[i].x, ks[i].y);
    for (int i = 0; i < 3; i++) {
        uint2 ku, kr, klo;
        tf2x32(ks[i].x, ks[i].y, 0u, 0u, ku.x, ku.y);   // split(k)[0] -> uniform key
        tf2x32(ks[i].x, ks[i].y, 0u, 1u, kr.x, kr.y);   // split(k)[1] -> randint key
        tf2x32(kr.x,    kr.y,    0u, 1u, klo.x, klo.y); // split(kr)[1] -> lower_bits key
        g_keys[2 * i]     = ku;
        g_keys[2 * i + 1] = klo;
    }
    for (int k = 0; k < KK; k++) {
        int c = k / 9, t = k % 9, ki = t / 3, kj = t % 3;
        g_tab[k].x = c * (HW * HW) + ki * HW + kj;   // + (oh-1)*56 + (ow-1) at use
        g_tab[k].y = (ki << 8) | kj;
    }
}

// ---------------- K1: weight quantization (quant_ste) ----------------
__global__ void k_wq(const float* __restrict__ w) {
    __shared__ float red[256];
    __shared__ float s_scale;
    float m = 0.0f;
    for (int i = threadIdx.x; i < CO * KK; i += 256) m = fmaxf(m, fabsf(w[i]));
    red[threadIdx.x] = m; __syncthreads();
    for (int s = 128; s > 0; s >>= 1) {
        if (threadIdx.x < s) red[threadIdx.x] = fmaxf(red[threadIdx.x], red[threadIdx.x + s]);
        __syncthreads();
    }
    if (threadIdx.x == 0) s_scale = __fadd_rn(__fdiv_rn(red[0], 127.0f), 1e-12f);
    __syncthreads();
    float sc = s_scale;
    for (int i = threadIdx.x; i < CO * KK; i += 256) {
        float ww = w[i];
        float r  = rintf(__fdiv_rn(ww, sc));
        r = fminf(127.0f, fmaxf(-128.0f, r));
        float q  = __fmul_rn(r, sc);
        g_wq[i]  = __fadd_rn(ww, __fsub_rn(q, ww));   // STE forward, literal
    }
}

// ---------------- K2: max|p| = max_k( max_l|xcol| * max_co|wq| ) ----------------
__global__ void k_scalep(const float* __restrict__ x) {
    int k = blockIdx.x;
    int c = k / 9, t = k % 9, ki = t / 3, kj = t % 3;
    __shared__ float red[128];
    float m = 0.0f;
    for (int l = threadIdx.x; l < LL; l += 128) {
        int oh = l / HW, ow = l % HW;
        int ih = oh + ki - 1, iw = ow + kj - 1;
        float v = 0.0f;
        if ((unsigned)ih < HW && (unsigned)iw < HW) v = x[(c * HW + ih) * HW + iw];
        m = fmaxf(m, fabsf(v));
    }
    red[threadIdx.x] = m; __syncthreads();
    for (int s = 64; s > 0; s >>= 1) {
        if (threadIdx.x < s) red[threadIdx.x] = fmaxf(red[threadIdx.x], red[threadIdx.x + s]);
        __syncthreads();
    }
    if (threadIdx.x == 0) {
        float wm = 0.0f;
        for (int co = 0; co < CO; co++) wm = fmaxf(wm, fabsf(g_wq[co * KK + k]));
        float p = __fmul_rn(red[0], wm);   // exact: fp mul rounding is monotone
        atomicMax(&g_maxp, __float_as_uint(p));
    }
}

// ---------------- K3: warp-per-row: bitflip + exact Brent-Kung scan + store c ----------------
// 288 = 9*32: every lane does exactly 9 elements -> warp always converged (ballot-safe).
// Scan runs entirely within one warp (__syncwarp only; zero block barriers).
__global__ void __launch_bounds__(128) k_main(const float* __restrict__ x) {
    const int wid = threadIdx.x >> 5;
    const int lid = threadIdx.x & 31;
    const int r   = blockIdx.x * 4 + wid;
    const int co = r / LL, l = r % LL;
    const int oh = l / HW, ow = l % HW;
    __shared__ float lv_all[4][574];   // per-warp scan levels: 288+144+72+36+18+9+4+2+1
    float* lv = lv_all[wid];

    const float scale_p = get_scale(&g_maxp);
    const float rcp_p   = __frcp_rn(scale_p);
    const uint2 ku  = g_keys[0];
    const uint2 klo = g_keys[1];
    const float* wrow = g_wq + co * KK;
    const int base = (oh - 1) * HW + (ow - 1);
    const uint32_t ridx = (uint32_t)r * (uint32_t)KK;

    if (oh >= 1 && oh < HW - 1 && ow >= 1 && ow < HW - 1) {
        // interior: no bounds checks (87% of rows)
        #pragma unroll
        for (int i = 0; i < 9; i++) {
            int k = i * 32 + lid;
            int2 tv = g_tab[k];
            float p = __fmul_rn(x[base + tv.x], wrow[k]);
            lv[k] = bitflip(p, scale_p, rcp_p, ku, klo, ridx + (uint32_t)k);
        }
    } else {
        #pragma unroll
        for (int i = 0; i < 9; i++) {
            int k = i * 32 + lid;
            int2 tv = g_tab[k];
            int ki = tv.y >> 8, kj = tv.y & 255;
            float xv = 0.0f;
            if ((unsigned)(oh - 1 + ki) < HW && (unsigned)(ow - 1 + kj) < HW)
                xv = x[base + tv.x];
            float p = __fmul_rn(xv, wrow[k]);
            lv[k] = bitflip(p, scale_p, rcp_p, ku, klo, ridx + (uint32_t)k);
        }
    }
    __syncwarp();

    // ---- up-sweep (exact jax associative_scan tree) ----
    // t=0: 288 -> 144
    for (int i = lid; i < 144; i += 32)
        lv[288 + i] = __fadd_rn(lv[2 * i], lv[2 * i + 1]);
    __syncwarp();
    // t=1: 144 -> 72
    for (int i = lid; i < 72; i += 32)
        lv[432 + i] = __fadd_rn(lv[288 + 2 * i], lv[288 + 2 * i + 1]);
    __syncwarp();
    // t=2: 72 -> 36
    for (int i = lid; i < 36; i += 32)
        lv[504 + i] = __fadd_rn(lv[432 + 2 * i], lv[432 + 2 * i + 1]);
    __syncwarp();
    // t=3: 36 -> 18
    if (lid < 18) lv[540 + lid] = __fadd_rn(lv[504 + 2 * lid], lv[504 + 2 * lid + 1]);
    __syncwarp();
    // t=4: 18 -> 9
    if (lid < 9) lv[558 + lid] = __fadd_rn(lv[540 + 2 * lid], lv[540 + 2 * lid + 1]);
    __syncwarp();
    // t=5: 9 -> 4
    if (lid < 4) lv[567 + lid] = __fadd_rn(lv[558 + 2 * lid], lv[558 + 2 * lid + 1]);
    __syncwarp();
    // t=6: 4 -> 2
    if (lid < 2) lv[571 + lid] = __fadd_rn(lv[567 + 2 * lid], lv[567 + 2 * lid + 1]);
    __syncwarp();
    // t=7: 2 -> 1
    if (lid < 1) lv[573] = __fadd_rn(lv[571], lv[572]);
    __syncwarp();

    // ---- down-sweep: s[2i+1]=child[i], s[2i+2]=child[i]+x[2i+2] ----
    // t=7: n=2
    if (lid < 1) lv[572] = lv[573];
    __syncwarp();
    // t=6: n=4, OFF=567, up=571
    if (lid < 2) {
        float sc = lv[571 + lid];
        bool has = (2 * lid + 2 < 4);
        float ev = has ? __fadd_rn(sc, lv[567 + 2 * lid + 2]) : 0.0f;
        lv[567 + 2 * lid + 1] = sc;
        if (has) lv[567 + 2 * lid + 2] = ev;
    }
    __syncwarp();
    // t=5: n=9, OFF=558, up=567
    if (lid < 4) {
        float sc = lv[567 + lid];
        bool has = (2 * lid + 2 < 9);
        float ev = has ? __fadd_rn(sc, lv[558 + 2 * lid + 2]) : 0.0f;
        lv[558 + 2 * lid + 1] = sc;
        if (has) lv[558 + 2 * lid + 2] = ev;
    }
    __syncwarp();
    // t=4: n=18, OFF=540, up=558
    if (lid < 9) {
        float sc = lv[558 + lid];
        bool has = (2 * lid + 2 < 18);
        float ev = has ? __fadd_rn(sc, lv[540 + 2 * lid + 2]) : 0.0f;
        lv[540 + 2 * lid + 1] = sc;
        if (has) lv[540 + 2 * lid + 2] = ev;
    }
    __syncwarp();
    // t=3: n=36, OFF=504, up=540
    if (lid < 18) {
        float sc = lv[540 + lid];
        bool has = (2 * lid + 2 < 36);
        float ev = has ? __fadd_rn(sc, lv[504 + 2 * lid + 2]) : 0.0f;
        lv[504 + 2 * lid + 1] = sc;
        if (has) lv[504 + 2 * lid + 2] = ev;
    }
    __syncwarp();
    // t=2: n=72, OFF=432, up=504
    for (int i = lid; i < 36; i += 32) {
        float sc = lv[504 + i];
        bool has = (2 * i + 2 < 72);
        float ev = has ? __fadd_rn(sc, lv[432 + 2 * i + 2]) : 0.0f;
        lv[432 + 2 * i + 1] = sc;
        if (has) lv[432 + 2 * i + 2] = ev;
    }
    __syncwarp();
    // t=1: n=144, OFF=288, up=432
    for (int i = lid; i < 72; i += 32) {
        float sc = lv[432 + i];
        bool has = (2 * i + 2 < 144);
        float ev = has ? __fadd_rn(sc, lv[288 + 2 * i + 2]) : 0.0f;
        lv[288 + 2 * i + 1] = sc;
        if (has) lv[288 + 2 * i + 2] = ev;
    }
    __syncwarp();
    // t=0: n=288, OFF=0, up=288
    for (int i = lid; i < 144; i += 32) {
        float sc = lv[288 + i];
        bool has = (2 * i + 2 < 288);
        float ev = has ? __fadd_rn(sc, lv[2 * i + 2]) : 0.0f;
        lv[2 * i + 1] = sc;
        if (has) lv[2 * i + 2] = ev;
    }
    __syncwarp();

    // write c row + per-warp max|c|
    float m = 0.0f;
    #pragma unroll
    for (int i = 0; i < 9; i++) {
        int k = i * 32 + lid;
        float cv = lv[k];
        g_c[(size_t)r * KK + k] = cv;
        m = fmaxf(m, fabsf(cv));
    }
    #pragma unroll
    for (int d = 16; d > 0; d >>= 1)
        m = fmaxf(m, __shfl_xor_sync(0xffffffffu, m, d));
    if (lid == 0) atomicMax(&g_maxc, __float_as_uint(m));
}

// ---------------- K4: warp-per-row: c_fi, y = c_fi[287] + sum_{k=1..286}(c_fi - c) ----------------
__global__ void __launch_bounds__(128) k_yrow() {
    const int wid = threadIdx.x >> 5;
    const int lid = threadIdx.x & 31;
    const int r   = blockIdx.x * 4 + wid;

    const float scale_c = get_scale(&g_maxc);
    const float rcp_c   = __frcp_rn(scale_c);
    const uint2 ku  = g_keys[2];
    const uint2 klo = g_keys[3];
    const uint32_t ridx = (uint32_t)r * (uint32_t)KK;
    const float* crow = g_c + (size_t)r * KK;

    float acc = 0.0f;
    float last = 0.0f;
    #pragma unroll
    for (int i = 0; i < 9; i++) {
        int k = i * 32 + lid;
        float cv = crow[k];
        float cf = bitflip(cv, scale_c, rcp_c, ku, klo, ridx + (uint32_t)k);
        if (k == KK - 1) last = cf;                         // lane 31, iter 8
        else if (k > 0) acc = __fadd_rn(acc, __fsub_rn(cf, cv));
    }
    #pragma unroll
    for (int d = 16; d > 0; d >>= 1)
        acc = __fadd_rn(acc, __shfl_xor_sync(0xffffffffu, acc, d));
    last = __shfl_sync(0xffffffffu, last, 31);
    if (lid == 0) {
        float y = __fadd_rn(last, acc);
        g_y[r] = y;
        atomicMax(&g_maxy, __float_as_uint(fabsf(y)));
    }
}

// ---------------- K5: final output bitflip (ROWS = 784*256, all warps full) ----------------
__global__ void k_out(float* __restrict__ out) {
    int i = blockIdx.x * 256 + threadIdx.x;
    if (i >= ROWS) return;
    const float scale_y = get_scale(&g_maxy);
    const float rcp_y   = __frcp_rn(scale_y);
    out[i] = bitflip(g_y[i], scale_y, rcp_y, g_keys[4], g_keys[5], (uint32_t)i);
}

// ---------------- launch ----------------
extern "C" void kernel_launch(void* const* d_in, const int* in_sizes, int n_in,
                              void* d_out, int out_size) {
    const float* x = (const float*)d_in[0];
    const float* w = (const float*)d_in[1];
    if (n_in >= 2 && in_sizes[0] == CO * KK && in_sizes[1] == CI * HW * HW) {
        const float* tmp = x; x = w; w = tmp;
    }
    k_init<<<1, 1>>>();
    k_wq<<<1, 256>>>(w);
    k_scalep<<<KK, 128>>>(x);
    k_main<<<ROWS / 4, 128>>>(x);
    k_yrow<<<ROWS / 4, 128>>>();
    k_out<<<(ROWS + 255) / 256, 256>>>((float*)d_out);
}

// round 11
// speedup vs baseline: 1.9541x; 1.1037x over previous
#include <cuda_runtime.h>
#include <cstdint>

// Problem dims
#define CI    32
#define HW    56
#define CO    64
#define KK    288          // CI*3*3
#define LL    3136         // 56*56
#define ROWS  200704       // CO*LL
#define NP    57802752     // ROWS*KK

// flip iff (bits64 >> 12) < MTH  <=>  u_f64 < float64(1e-3*8)
#define MTH   36028797018964ULL

// Scratch (device globals: no allocations allowed)
__device__ float    g_wq[CO * KK];
__device__ float    g_c[NP];          // 231 MB cumsum storage
__device__ float    g_y[ROWS];
__device__ unsigned g_maxp, g_maxc, g_maxy;
__device__ uint2    g_keys[6];        // (ku, klo) for P, C, Y stages
__device__ int2     g_tab[KK];        // per-k: x-offset delta, (ki<<8)|kj

// ---------------- Threefry2x32 (exact JAX rotation/key schedule) ----------------
__device__ __forceinline__ void tf2x32(uint32_t k0, uint32_t k1,
                                       uint32_t x0, uint32_t x1,
                                       uint32_t& o0, uint32_t& o1) {
    uint32_t ks2 = k0 ^ k1 ^ 0x1BD11BDAu;
#define TFR(r) { x0 += x1; x1 = __funnelshift_l(x1, x1, (r)); x1 ^= x0; }
    x0 += k0; x1 += k1;
    TFR(13) TFR(15) TFR(26) TFR(6)
    x0 += k1;  x1 += ks2 + 1u;
    TFR(17) TFR(29) TFR(16) TFR(24)
    x0 += ks2; x1 += k0 + 2u;
    TFR(13) TFR(15) TFR(26) TFR(6)
    x0 += k0;  x1 += k1 + 3u;
    TFR(17) TFR(29) TFR(16) TFR(24)
    x0 += k1;  x1 += ks2 + 4u;
    TFR(13) TFR(15) TFR(26) TFR(6)
    x0 += ks2; x1 += k0 + 5u;
#undef TFR
    o0 = x0; o1 = x1;
}

// u-draw: flip decision only (f64 uniform < 0.008, integer-exact)
__device__ __forceinline__ bool flip_draw(uint2 ku, uint32_t idx) {
    uint32_t ua, ub;
    tf2x32(ku.x, ku.y, 0u, idx, ua, ub);
    uint64_t b = ((uint64_t)ua << 32) | (uint64_t)ub;
    return (b >> 12) < MTH;
}
// pos-draw: mask bit (int64 randint % 8 -> low word & 7)
__device__ __forceinline__ int pos_mask(uint2 klo, uint32_t idx) {
    uint32_t pa, pb;
    tf2x32(klo.x, klo.y, 0u, idx, pa, pb);
    return 1 << (int)(pb & 7u);
}

// Exact RN(x/s) in 3 ops given r = RN(1/s) (Markstein; fma required).
__device__ __forceinline__ float div_exact(float x, float s, float r) {
    float q0 = __fmul_rn(x, r);
    float e  = __fmaf_rn(-s, q0, x);
    return __fmaf_rn(e, r, q0);
}

// Flip-free quant+STE: qf = q&255 sign-extends back to q, so qs == r exactly.
__device__ __forceinline__ float quant_noflip(float x, float scale, float rcp) {
    float t = div_exact(x, scale, rcp);
    float r = rintf(t);
    r = fminf(127.0f, fmaxf(-128.0f, r));
    float y = __fmul_rn(r, scale);
    return __fadd_rn(x, __fsub_rn(y, x));
}
// Quant+STE with flip mask m (m may be 0 -> identical to noflip).
__device__ __forceinline__ float quant_flip(float x, float scale, float rcp, int m) {
    float t = div_exact(x, scale, rcp);
    float r = rintf(t);
    r = fminf(127.0f, fmaxf(-128.0f, r));
    int qf = ((int)r & 255) ^ m;
    float qs = (float)(signed char)(qf);        // two's-complement view
    float y  = __fmul_rn(qs, scale);
    return __fadd_rn(x, __fsub_rn(y, x));
}

__device__ __forceinline__ float get_scale(const unsigned* bits) {
    return __fadd_rn(__fdiv_rn(__uint_as_float(*bits), 127.0f), 1e-12f);
}

// ---------------- K0: reset accumulators, subkeys, per-k table ----------------
__global__ void k_init() {
    g_maxp = 0u; g_maxc = 0u; g_maxy = 0u;
    uint2 ks[3];
    for (uint32_t i = 0; i < 3; i++) tf2x32(0u, 42u, 0u, i, ks[i].x, ks[i].y);
    for (int i = 0; i < 3; i++) {
        uint2 ku, kr, klo;
        tf2x32(ks[i].x, ks[i].y, 0u, 0u, ku.x, ku.y);   // split(k)[0] -> uniform key
        tf2x32(ks[i].x, ks[i].y, 0u, 1u, kr.x, kr.y);   // split(k)[1] -> randint key
        tf2x32(kr.x,    kr.y,    0u, 1u, klo.x, klo.y); // split(kr)[1] -> lower_bits key
        g_keys[2 * i]     = ku;
        g_keys[2 * i + 1] = klo;
    }
    for (int k = 0; k < KK; k++) {
        int c = k / 9, t = k % 9, ki = t / 3, kj = t % 3;
        g_tab[k].x = c * (HW * HW) + ki * HW + kj;   // + (oh-1)*56 + (ow-1) at use
        g_tab[k].y = (ki << 8) | kj;
    }
}

// ---------------- K1: weight quantization (quant_ste) ----------------
__global__ void k_wq(const float* __restrict__ w) {
    __shared__ float red[256];
    __shared__ float s_scale;
    float m = 0.0f;
    for (int i = threadIdx.x; i < CO * KK; i += 256) m = fmaxf(m, fabsf(w[i]));
    red[threadIdx.x] = m; __syncthreads();
    for (int s = 128; s > 0; s >>= 1) {
        if (threadIdx.x < s) red[threadIdx.x] = fmaxf(red[threadIdx.x], red[threadIdx.x + s]);
        __syncthreads();
    }
    if (threadIdx.x == 0) s_scale = __fadd_rn(__fdiv_rn(red[0], 127.0f), 1e-12f);
    __syncthreads();
    float sc = s_scale;
    for (int i = threadIdx.x; i < CO * KK; i += 256) {
        float ww = w[i];
        float r  = rintf(__fdiv_rn(ww, sc));
        r = fminf(127.0f, fmaxf(-128.0f, r));
        float q  = __fmul_rn(r, sc);
        g_wq[i]  = __fadd_rn(ww, __fsub_rn(q, ww));   // STE forward, literal
    }
}

// ---------------- K2: max|p| = max_k( max_l|xcol| * max_co|wq| ) ----------------
__global__ void k_scalep(const float* __restrict__ x) {
    int k = blockIdx.x;
    int c = k / 9, t = k % 9, ki = t / 3, kj = t % 3;
    __shared__ float red[128];
    float m = 0.0f;
    for (int l = threadIdx.x; l < LL; l += 128) {
        int oh = l / HW, ow = l % HW;
        int ih = oh + ki - 1, iw = ow + kj - 1;
        float v = 0.0f;
        if ((unsigned)ih < HW && (unsigned)iw < HW) v = x[(c * HW + ih) * HW + iw];
        m = fmaxf(m, fabsf(v));
    }
    red[threadIdx.x] = m; __syncthreads();
    for (int s = 64; s > 0; s >>= 1) {
        if (threadIdx.x < s) red[threadIdx.x] = fmaxf(red[threadIdx.x], red[threadIdx.x + s]);
        __syncthreads();
    }
    if (threadIdx.x == 0) {
        float wm = 0.0f;
        for (int co = 0; co < CO; co++) wm = fmaxf(wm, fabsf(g_wq[co * KK + k]));
        float p = __fmul_rn(red[0], wm);   // exact: fp mul rounding is monotone
        atomicMax(&g_maxp, __float_as_uint(p));
    }
}

// p(k) loader shared by main loop and fix-up
__device__ __forceinline__ float load_p(const float* __restrict__ x,
                                        const float* __restrict__ wrow,
                                        int base, int oh, int ow, bool interior, int k) {
    int2 tv = g_tab[k];
    float xv = 0.0f;
    if (interior) {
        xv = x[base + tv.x];
    } else {
        int ki = tv.y >> 8, kj = tv.y & 255;
        if ((unsigned)(oh - 1 + ki) < HW && (unsigned)(ow - 1 + kj) < HW)
            xv = x[base + tv.x];
    }
    return __fmul_rn(xv, wrow[k]);
}

// ---------------- K3: warp-per-row: deferred-flip bitflip + exact scan + fused store ----------------
__global__ void __launch_bounds__(128) k_main(const float* __restrict__ x) {
    const int wid = threadIdx.x >> 5;
    const int lid = threadIdx.x & 31;
    const int r   = blockIdx.x * 4 + wid;
    const int co = r / LL, l = r % LL;
    const int oh = l / HW, ow = l % HW;
    __shared__ __align__(16) float lv_all[4][576];  // levels: 288+144+72+36+18+9+4+2+1
    float* lv = lv_all[wid];

    const float scale_p = get_scale(&g_maxp);
    const float rcp_p   = __frcp_rn(scale_p);
    const uint2 ku  = g_keys[0];
    const uint2 klo = g_keys[1];
    const float* wrow = g_wq + co * KK;
    const int base = (oh - 1) * HW + (ow - 1);
    const bool interior = (oh >= 1 && oh < HW - 1 && ow >= 1 && ow < HW - 1);
    const uint32_t ridx = (uint32_t)r * (uint32_t)KK;

    // ---- main pass: u-draw + flip-free quant; record flip mask ----
    unsigned fmask = 0u;
    if (interior) {
        #pragma unroll
        for (int i = 0; i < 9; i++) {
            int k = i * 32 + lid;
            float p = __fmul_rn(x[base + g_tab[k].x], wrow[k]);
            if (flip_draw(ku, ridx + (uint32_t)k)) fmask |= (1u << i);
            lv[k] = quant_noflip(p, scale_p, rcp_p);
        }
    } else {
        #pragma unroll
        for (int i = 0; i < 9; i++) {
            int k = i * 32 + lid;
            float p = load_p(x, wrow, base, oh, ow, false, k);
            if (flip_draw(ku, ridx + (uint32_t)k)) fmask |= (1u << i);
            lv[k] = quant_noflip(p, scale_p, rcp_p);
        }
    }
    // ---- fix-up: rare flips (E ~2.3 per row-warp), each lane owns its k's ----
    while (__any_sync(0xffffffffu, fmask != 0u)) {
        if (fmask) {
            int i = __ffs(fmask) - 1; fmask &= fmask - 1u;
            int k = i * 32 + lid;
            float p = load_p(x, wrow, base, oh, ow, interior, k);
            int m = pos_mask(klo, ridx + (uint32_t)k);
            lv[k] = quant_flip(p, scale_p, rcp_p, m);
        }
    }
    __syncwarp();

    // ---- up-sweep (exact jax associative_scan tree), float2 reads ----
    const float2* lv2 = (const float2*)lv;
    for (int i = lid; i < 144; i += 32) {            // t=0: 288->144
        float2 v = lv2[i];
        lv[288 + i] = __fadd_rn(v.x, v.y);
    }
    __syncwarp();
    for (int i = lid; i < 72; i += 32) {             // t=1: 144->72
        float2 v = lv2[144 + i];
        lv[432 + i] = __fadd_rn(v.x, v.y);
    }
    __syncwarp();
    for (int i = lid; i < 36; i += 32) {             // t=2: 72->36
        float2 v = lv2[216 + i];
        lv[504 + i] = __fadd_rn(v.x, v.y);
    }
    __syncwarp();
    if (lid < 18) lv[540 + lid] = __fadd_rn(lv[504 + 2 * lid], lv[504 + 2 * lid + 1]);
    __syncwarp();
    if (lid < 9)  lv[558 + lid] = __fadd_rn(lv[540 + 2 * lid], lv[540 + 2 * lid + 1]);
    __syncwarp();
    if (lid < 4)  lv[567 + lid] = __fadd_rn(lv[558 + 2 * lid], lv[558 + 2 * lid + 1]);
    __syncwarp();
    if (lid < 2)  lv[571 + lid] = __fadd_rn(lv[567 + 2 * lid], lv[567 + 2 * lid + 1]);
    __syncwarp();
    if (lid < 1)  lv[573] = __fadd_rn(lv[571], lv[572]);
    __syncwarp();

    // ---- down-sweep: s[2i+1]=child[i], s[2i+2]=child[i]+x[2i+2] ----
    if (lid < 1) lv[572] = lv[573];                  // t=7: n=2
    __syncwarp();
    if (lid < 2) {                                   // t=6: n=4, OFF=567, up=571
        float sc = lv[571 + lid];
        bool has = (2 * lid + 2 < 4);
        float ev = has ? __fadd_rn(sc, lv[567 + 2 * lid + 2]) : 0.0f;
        lv[567 + 2 * lid + 1] = sc;
        if (has) lv[567 + 2 * lid + 2] = ev;
    }
    __syncwarp();
    if (lid < 4) {                                   // t=5: n=9, OFF=558, up=567
        float sc = lv[567 + lid];
        bool has = (2 * lid + 2 < 9);
        float ev = has ? __fadd_rn(sc, lv[558 + 2 * lid + 2]) : 0.0f;
        lv[558 + 2 * lid + 1] = sc;
        if (has) lv[558 + 2 * lid + 2] = ev;
    }
    __syncwarp();
    if (lid < 9) {                                   // t=4: n=18, OFF=540, up=558
        float sc = lv[558 + lid];
        bool has = (2 * lid + 2 < 18);
        float ev = has ? __fadd_rn(sc, lv[540 + 2 * lid + 2]) : 0.0f;
        lv[540 + 2 * lid + 1] = sc;
        if (has) lv[540 + 2 * lid + 2] = ev;
    }
    __syncwarp();
    if (lid < 18) {                                  // t=3: n=36, OFF=504, up=540
        float sc = lv[540 + lid];
        bool has = (2 * lid + 2 < 36);
        float ev = has ? __fadd_rn(sc, lv[504 + 2 * lid + 2]) : 0.0f;
        lv[504 + 2 * lid + 1] = sc;
        if (has) lv[504 + 2 * lid + 2] = ev;
    }
    __syncwarp();
    for (int i = lid; i < 36; i += 32) {             // t=2: n=72, OFF=432, up=504
        float sc = lv[504 + i];
        bool has = (2 * i + 2 < 72);
        float ev = has ? __fadd_rn(sc, lv[432 + 2 * i + 2]) : 0.0f;
        lv[432 + 2 * i + 1] = sc;
        if (has) lv[432 + 2 * i + 2] = ev;
    }
    __syncwarp();
    for (int i = lid; i < 72; i += 32) {             // t=1: n=144, OFF=288, up=432
        float sc = lv[432 + i];
        bool has = (2 * i + 2 < 144);
        float ev = has ? __fadd_rn(sc, lv[288 + 2 * i + 2]) : 0.0f;
        lv[288 + 2 * i + 1] = sc;
        if (has) lv[288 + 2 * i + 2] = ev;
    }
    __syncwarp();

    // ---- final level fused with gmem store + max|c| ----
    // c[0]=x0[0]; c[2i+1]=s1[i]; c[2i+2]=s1[i]+x0[2i+2]
    float* crow = g_c + (size_t)r * KK;
    float m = 0.0f;
    for (int i = lid; i < 144; i += 32) {
        float sc = lv[288 + i];
        crow[2 * i + 1] = sc; m = fmaxf(m, fabsf(sc));
        if (i == 0) { float c0 = lv[0]; crow[0] = c0; m = fmaxf(m, fabsf(c0)); }
        if (2 * i + 2 < KK) {
            float ev = __fadd_rn(sc, lv[2 * i + 2]);
            crow[2 * i + 2] = ev; m = fmaxf(m, fabsf(ev));
        }
    }
    #pragma unroll
    for (int d = 16; d > 0; d >>= 1)
        m = fmaxf(m, __shfl_xor_sync(0xffffffffu, m, d));
    if (lid == 0) atomicMax(&g_maxc, __float_as_uint(m));
}

// ---------------- K4: warp-per-row: c_fi, y = c_fi[287] + sum_{k=1..286}(c_fi - c) ----------------
// Deferred flips: in-loop accumulates only unflipped terms; flipped terms added in fix-up.
__global__ void __launch_bounds__(128) k_yrow() {
    const int wid = threadIdx.x >> 5;
    const int lid = threadIdx.x & 31;
    const int r   = blockIdx.x * 4 + wid;

    const float scale_c = get_scale(&g_maxc);
    const float rcp_c   = __frcp_rn(scale_c);
    const uint2 ku  = g_keys[2];
    const uint2 klo = g_keys[3];
    const uint32_t ridx = (uint32_t)r * (uint32_t)KK;
    const float* crow = g_c + (size_t)r * KK;

    float acc = 0.0f;
    float last = 0.0f;
    unsigned fmask = 0u;
    #pragma unroll
    for (int i = 0; i < 9; i++) {
        int k = i * 32 + lid;
        float cv = crow[k];
        bool flip = flip_draw(ku, ridx + (uint32_t)k);
        if (flip) fmask |= (1u << i);
        float cf = quant_noflip(cv, scale_c, rcp_c);
        if (!flip) {
            if (k == KK - 1) last = cf;                     // lane 31, iter 8
            else if (k > 0) acc = __fadd_rn(acc, __fsub_rn(cf, cv));
        }
    }
    while (__any_sync(0xffffffffu, fmask != 0u)) {
        if (fmask) {
            int i = __ffs(fmask) - 1; fmask &= fmask - 1u;
            int k = i * 32 + lid;
            float cv = crow[k];
            int m = pos_mask(klo, ridx + (uint32_t)k);
            float cf = quant_flip(cv, scale_c, rcp_c, m);
            if (k == KK - 1) last = cf;
            else if (k > 0) acc = __fadd_rn(acc, __fsub_rn(cf, cv));
        }
    }
    #pragma unroll
    for (int d = 16; d > 0; d >>= 1)
        acc = __fadd_rn(acc, __shfl_xor_sync(0xffffffffu, acc, d));
    last = __shfl_sync(0xffffffffu, last, 31);
    if (lid == 0) {
        float y = __fadd_rn(last, acc);
        g_y[r] = y;
        atomicMax(&g_maxy, __float_as_uint(fabsf(y)));
    }
}

// ---------------- K5: final output bitflip (ROWS = 784*256 exactly, all warps full) ----------------
__global__ void k_out(float* __restrict__ out) {
    int i = blockIdx.x * 256 + threadIdx.x;
    const float scale_y = get_scale(&g_maxy);
    const float rcp_y   = __frcp_rn(scale_y);
    float v = g_y[i];
    bool flip = flip_draw(g_keys[4], (uint32_t)i);
    float o;
    if (__ballot_sync(0xffffffffu, flip)) {
        int m = flip ? pos_mask(g_keys[5], (uint32_t)i) : 0;
        o = quant_flip(v, scale_y, rcp_y, m);       // m=0 path == noflip exactly
    } else {
        o = quant_noflip(v, scale_y, rcp_y);
    }
    out[i] = o;
}

// ---------------- launch ----------------
extern "C" void kernel_launch(void* const* d_in, const int* in_sizes, int n_in,
                              void* d_out, int out_size) {
    const float* x = (const float*)d_in[0];
    const float* w = (const float*)d_in[1];
    if (n_in >= 2 && in_sizes[0] == CO * KK && in_sizes[1] == CI * HW * HW) {
        const float* tmp = x; x = w; w = tmp;
    }
    k_init<<<1, 1>>>();
    k_wq<<<1, 256>>>(w);
    k_scalep<<<KK, 128>>>(x);
    k_main<<<ROWS / 4, 128>>>(x);
    k_yrow<<<ROWS / 4, 128>>>();
    k_out<<<ROWS / 256, 256>>>((float*)d_out);
}